// round 17
// baseline (speedup 1.0000x reference)
#include <cuda_runtime.h>
#include <math.h>
#include <cstdint>

#define NB  512
#define NK  64
#define NC  2048
#define TPC 128
#define CT  (NC / TPC)           // 16 channel tiles per batch

__device__ __forceinline__ float ex2a(float x) {
    float r; asm("ex2.approx.ftz.f32 %0, %1;" : "=f"(r) : "f"(x)); return r;
}
__device__ __forceinline__ float lg2a(float x) {
    float r; asm("lg2.approx.ftz.f32 %0, %1;" : "=f"(r) : "f"(x)); return r;
}
__device__ __forceinline__ uint32_t tf32b(float x) {
    uint32_t r; asm("cvt.rna.tf32.f32 %0, %1;" : "=r"(r) : "f"(x)); return r;
}
__device__ __forceinline__ void mma8(float* c, const uint32_t* a,
                                     uint32_t b0, uint32_t b1) {
    asm volatile(
        "mma.sync.aligned.m16n8k8.row.col.f32.tf32.tf32.f32 "
        "{%0,%1,%2,%3}, {%4,%5,%6,%7}, {%8,%9}, {%0,%1,%2,%3};"
        : "+f"(c[0]), "+f"(c[1]), "+f"(c[2]), "+f"(c[3])
        : "r"(a[0]), "r"(a[1]), "r"(a[2]), "r"(a[3]), "r"(b0), "r"(b1));
}

__global__ __launch_bounds__(TPC)
void mix_mma_kernel(const float* __restrict__ mo,
                    const float* __restrict__ X,
                    float* __restrict__ out) {
    // A: 3 steps x 128 rows x 8 k-cols (features: fhi | flo | fhi)
    // B: 3 steps x 8 k-rows x 64 mixtures, padded to 72 (coeffs: chi | chi | clo)
    __shared__ float sA[3][TPC][8];
    __shared__ float sB[3][8][72];

    const int tid  = threadIdx.x;
    const int lane = tid & 31;
    const int w    = tid >> 5;
    const int g    = lane >> 2;     // groupID
    const int tg   = lane & 3;      // threadID_in_group
    const int b    = blockIdx.x >> 4;
    const int ct   = blockIdx.x & (CT - 1);

    // --- zero smem (pad cols/rows must be 0) ---
    {
        float4 z = make_float4(0.f, 0.f, 0.f, 0.f);
        float4* pa = reinterpret_cast<float4*>(&sA[0][0][0]);
        #pragma unroll
        for (int i = tid; i < 3 * TPC * 8 / 4; i += TPC) pa[i] = z;
        float4* pb = reinterpret_cast<float4*>(&sB[0][0][0]);
        for (int i = tid; i < 3 * 8 * 72 / 4; i += TPC) pb[i] = z;
    }
    __syncthreads();

    // --- A tile: per-channel features, tf32 hi/lo split ---
    {
        const int c = ct * TPC + tid;
        float2 v = reinterpret_cast<const float2*>(X)[(size_t)b * NC + c];
        float f[6];
        f[0] = v.x * v.x; f[1] = v.x * v.y; f[2] = v.y * v.y;
        f[3] = v.x;       f[4] = v.y;       f[5] = 1.0f;
        #pragma unroll
        for (int j = 0; j < 6; j++) {
            float hi = __uint_as_float(tf32b(f[j]));
            float lo = __uint_as_float(tf32b(f[j] - hi));
            sA[0][tid][j] = hi;
            sA[1][tid][j] = lo;
            sA[2][tid][j] = hi;
        }
    }

    // --- B tile: per-mixture coefficients (W folded into F), hi/lo split ---
    if (tid < NK) {
        const float* p = mo + ((size_t)b * NK + tid) * 6;
        float wgt = p[0], m1 = p[1], m2 = p[2], s1 = p[3], s2 = p[4], r = p[5];

        float omr2 = 1.0f - r * r;
        float inv  = 1.0f / omr2;
        float is1  = 1.0f / s1;
        float is2  = 1.0f / s2;

        const float L2E = 1.4426950408889634f;
        float A = -0.5f * inv * is1 * is1 * L2E;
        float B =  r    * inv * is1 * is2 * L2E;
        float C = -0.5f * inv * is2 * is2 * L2E;
        float D = -(2.0f * A * m1 + B * m2);
        float E = -(2.0f * C * m2 + B * m1);
        float W = wgt * is1 * is2 * rsqrtf(omr2) * 0.15915494309189535f;
        float F = A * m1 * m1 + B * m1 * m2 + C * m2 * m2 + lg2a(W);

        float cf[6] = {A, B, C, D, E, F};
        #pragma unroll
        for (int j = 0; j < 6; j++) {
            float hi = __uint_as_float(tf32b(cf[j]));
            float lo = __uint_as_float(tf32b(cf[j] - hi));
            sB[0][j][tid] = hi;
            sB[1][j][tid] = hi;
            sB[2][j][tid] = lo;
        }
    }
    __syncthreads();

    // --- load A fragments (2 m-tiles x 3 steps x 4 regs, held in registers) ---
    uint32_t af[2][3][4];
    #pragma unroll
    for (int mt = 0; mt < 2; mt++) {
        const int r0 = w * 32 + mt * 16 + g;
        #pragma unroll
        for (int s = 0; s < 3; s++) {
            af[mt][s][0] = __float_as_uint(sA[s][r0][tg]);
            af[mt][s][1] = __float_as_uint(sA[s][r0 + 8][tg]);
            af[mt][s][2] = __float_as_uint(sA[s][r0][tg + 4]);
            af[mt][s][3] = __float_as_uint(sA[s][r0 + 8][tg + 4]);
        }
    }

    float acc[2][8][4];
    #pragma unroll
    for (int mt = 0; mt < 2; mt++)
        #pragma unroll
        for (int nt = 0; nt < 8; nt++)
            #pragma unroll
            for (int i = 0; i < 4; i++) acc[mt][nt][i] = 0.f;

    // --- MMA: 8 n-tiles x 3 accumulating K-steps x 2 m-tiles ---
    #pragma unroll
    for (int nt = 0; nt < 8; nt++) {
        #pragma unroll
        for (int s = 0; s < 3; s++) {
            uint32_t b0 = __float_as_uint(sB[s][tg][nt * 8 + g]);
            uint32_t b1 = __float_as_uint(sB[s][tg + 4][nt * 8 + g]);
            mma8(acc[0][nt], af[0][s], b0, b1);
            mma8(acc[1][nt], af[1][s], b0, b1);
        }
    }

    // --- epilogue: ex2 each q, sum over the 64 mixtures, quad-reduce ---
    const size_t obase = (size_t)b * NC + ct * TPC;
    #pragma unroll
    for (int mt = 0; mt < 2; mt++) {
        float p0 = 0.f, p1 = 0.f, p2 = 0.f, p3 = 0.f;
        #pragma unroll
        for (int nt = 0; nt < 8; nt++) {
            p0 += ex2a(acc[mt][nt][0]);
            p1 += ex2a(acc[mt][nt][1]);
            p2 += ex2a(acc[mt][nt][2]);
            p3 += ex2a(acc[mt][nt][3]);
        }
        float q0 = p0 + p1;   // row r0, this thread's 16 columns
        float q1 = p2 + p3;   // row r0+8
        q0 += __shfl_xor_sync(0xffffffffu, q0, 1);
        q0 += __shfl_xor_sync(0xffffffffu, q0, 2);
        q1 += __shfl_xor_sync(0xffffffffu, q1, 1);
        q1 += __shfl_xor_sync(0xffffffffu, q1, 2);
        if (tg == 0) {
            const int r0 = w * 32 + mt * 16 + g;
            out[obase + r0]     = q0;
            out[obase + r0 + 8] = q1;
        }
    }
}

extern "C" void kernel_launch(void* const* d_in, const int* in_sizes, int n_in,
                              void* d_out, int out_size) {
    const float* mo = (const float*)d_in[0];   // model_out: (512, 64, 6) f32
    const float* X  = (const float*)d_in[1];   // X:         (512, 2048, 2) f32
    float* out      = (float*)d_out;           // out:       (512, 2048) f32
    (void)in_sizes; (void)n_in; (void)out_size;

    mix_mma_kernel<<<NB * CT, TPC>>>(mo, X, out);
}